// round 2
// baseline (speedup 1.0000x reference)
#include <cuda_runtime.h>
#include <math.h>

#define NB 64
#define NS 8192
#define NW 64
#define NM 16
#define NC 32
#define NL 4
#define NSPLIT 16
#define SCH (NS / NSPLIT)

// ---------------- device scratch (no cudaMalloc allowed) ----------------
__device__ float g_h[2][NB * NW * NS];        // ping-pong activations (b,i,s)
__device__ float g_tab[NC * NS];              // rows 0..15 cos(2pi k s/S), 16..31 sin
__device__ float g_ftp[NSPLIT][NB * NW * NC]; // split-K partial DFT sums
__device__ float g_coef[NB * NW * NC];        // per (b,o): A(cos) rows 0..15, B(sin) rows 16..31

// ---------------- packed f32x2 helpers ----------------
static __device__ __forceinline__ void fma2(unsigned long long& d,
                                            unsigned long long a,
                                            unsigned long long b) {
    asm("fma.rn.f32x2 %0, %1, %2, %0;" : "+l"(d) : "l"(a), "l"(b));
}
static __device__ __forceinline__ unsigned long long pk2(float v) {
    unsigned long long r;
    asm("mov.b64 %0, {%1, %1};" : "=l"(r) : "f"(v));
    return r;
}
static __device__ __forceinline__ float2 up2(unsigned long long p) {
    float2 r;
    asm("mov.b64 {%0, %1}, %2;" : "=f"(r.x), "=f"(r.y) : "l"(p));
    return r;
}

// fast accurate tanh: 2 MUFU (EX2 + RCP), ~1e-6 abs error, no branches
static __device__ __forceinline__ float ftanh(float x) {
    float ax = fminf(fabsf(x), 10.0f);
    float e = __expf(2.0f * ax);                    // MUFU.EX2 path
    float t = (e - 1.0f) * __fdividef(1.0f, e + 1.0f); // MUFU.RCP path
    return copysignf(t, x);
}

// ================= basis table =================
__global__ void k_tab() {
    int s = blockIdx.x * 256 + threadIdx.x;
    if (s >= NS) return;
#pragma unroll
    for (int k = 0; k < NM; k++) {
        int ph = (k * s) & (NS - 1);
        float ang = (float)((double)ph * (6.283185307179586476925287 / (double)NS));
        float c, sn;
        sincosf(ang, &c, &sn);
        g_tab[k * NS + s] = c;
        g_tab[(k + NM) * NS + s] = sn;
    }
}

// ================= lift =================
__global__ void __launch_bounds__(256) k_lift(const float* __restrict__ x,
                                              const float* __restrict__ pw,
                                              const float* __restrict__ pb) {
    __shared__ float w0[NW], w1[NW], bb[NW];
    int t = threadIdx.x;
    if (t < NW) { w0[t] = pw[t]; w1[t] = pw[NW + t]; bb[t] = pb[t]; }
    __syncthreads();
    int b = blockIdx.y;
    int s = blockIdx.x * 256 + t;
    float2 xv = ((const float2*)x)[b * NS + s];
    float* dst = &g_h[0][(size_t)(b * NW) * NS + s];
#pragma unroll 8
    for (int i = 0; i < NW; i++)
        dst[(size_t)i * NS] = fmaf(xv.x, w0[i], fmaf(xv.y, w1[i], bb[i]));
}

// ================= forward DFT partials =================
// block = (split, b); 64 threads; out C[i][kc] (64x32) over 512-sample chunk.
// thread tile: 8 i (ig*4+c, +32) x 4 kc (kg*4..+3), f32x2 packed along i.
__global__ void __launch_bounds__(64) k_fwd(int cur) {
    __shared__ float hT[32 * 68];   // [kk][i], 16B-aligned rows
    __shared__ float tt[32 * 36];   // [kk][kc]
    int t = threadIdx.x;
    int ig = t & 7, kg = t >> 3;
    int b = blockIdx.y;
    int s0 = blockIdx.x * SCH;
    const float* hb = g_h[cur] + (size_t)(b * NW) * NS;

    unsigned long long acc[2][2][4];
#pragma unroll
    for (int h = 0; h < 2; h++)
#pragma unroll
        for (int p = 0; p < 2; p++)
#pragma unroll
            for (int k = 0; k < 4; k++) acc[h][p][k] = 0ull;

    for (int ts = 0; ts < SCH; ts += 32) {
#pragma unroll
        for (int j = 0; j < 32; j++) {
            int idx = j * 64 + t;
            int i = idx >> 5, kk = idx & 31;
            hT[kk * 68 + i] = hb[(size_t)i * NS + s0 + ts + kk];
        }
#pragma unroll
        for (int j = 0; j < 16; j++) {
            int idx = j * 64 + t;
            int k = idx >> 5, kk = idx & 31;
            tt[kk * 36 + k] = g_tab[k * NS + s0 + ts + kk];
        }
        __syncthreads();
#pragma unroll 8
        for (int kk = 0; kk < 32; kk++) {
            ulonglong2 A0 = *(const ulonglong2*)&hT[kk * 68 + ig * 4];
            ulonglong2 A1 = *(const ulonglong2*)&hT[kk * 68 + 32 + ig * 4];
            float4 bv = *(const float4*)&tt[kk * 36 + kg * 4];
            unsigned long long b0 = pk2(bv.x), b1 = pk2(bv.y),
                               b2 = pk2(bv.z), b3 = pk2(bv.w);
            fma2(acc[0][0][0], A0.x, b0); fma2(acc[0][0][1], A0.x, b1);
            fma2(acc[0][0][2], A0.x, b2); fma2(acc[0][0][3], A0.x, b3);
            fma2(acc[0][1][0], A0.y, b0); fma2(acc[0][1][1], A0.y, b1);
            fma2(acc[0][1][2], A0.y, b2); fma2(acc[0][1][3], A0.y, b3);
            fma2(acc[1][0][0], A1.x, b0); fma2(acc[1][0][1], A1.x, b1);
            fma2(acc[1][0][2], A1.x, b2); fma2(acc[1][0][3], A1.x, b3);
            fma2(acc[1][1][0], A1.y, b0); fma2(acc[1][1][1], A1.y, b1);
            fma2(acc[1][1][2], A1.y, b2); fma2(acc[1][1][3], A1.y, b3);
        }
        __syncthreads();
    }
    float* fp = g_ftp[blockIdx.x] + (b * NW) * NC;
#pragma unroll
    for (int h = 0; h < 2; h++)
#pragma unroll
        for (int p = 0; p < 2; p++)
#pragma unroll
            for (int k = 0; k < 4; k++) {
                int i = h * 32 + ig * 4 + p * 2;
                float2 v = up2(acc[h][p][k]);
                fp[i * NC + kg * 4 + k] = v.x;
                fp[(i + 1) * NC + kg * 4 + k] = v.y;
            }
}

// ================= mode mix -> inverse coefficients =================
__global__ void __launch_bounds__(128) k_mix(const float* __restrict__ wr,
                                             const float* __restrict__ wi,
                                             const float* __restrict__ cb, int l) {
    __shared__ float frs[NW * NM], fis[NW * NM];
    int t = threadIdx.x, b = blockIdx.x;
    for (int idx = t; idx < NW * NC; idx += 128) {
        int i = idx >> 5, kc = idx & 31;
        float v = 0.f;
#pragma unroll
        for (int sp = 0; sp < NSPLIT; sp++) v += g_ftp[sp][(b * NW + i) * NC + kc];
        v *= (1.0f / NS);
        if (kc < NM) frs[i * NM + kc] = v;        // Re(ft) = +cos-sum/S
        else fis[i * NM + (kc - NM)] = -v;        // Im(ft) = -sin-sum/S
    }
    __syncthreads();
    const float* wrl = wr + l * NW * NW * NM;
    const float* wil = wi + l * NW * NW * NM;
    for (int idx = t; idx < NW * NM; idx += 128) {
        int o = idx >> 4, k = idx & 15;
        float sr = 0.f, si = 0.f;
#pragma unroll 8
        for (int i = 0; i < NW; i++) {
            float fr = frs[i * NM + k], fi = fis[i * NM + k];
            float a = wrl[(i * NW + o) * NM + k];
            float c = wil[(i * NW + o) * NM + k];
            sr = fmaf(fr, a, sr); sr = fmaf(-fi, c, sr);
            si = fmaf(fr, c, si); si = fmaf(fi, a, si);
        }
        float* cf = g_coef + (b * NW + o) * NC;
        if (k == 0) { cf[0] = sr + cb[l * NW + o]; cf[NM] = 0.f; }
        else        { cf[k] = 2.f * sr; cf[NM + k] = -2.f * si; }
    }
}

// ================= fused irfft + 1x1 conv + tanh =================
// out h_new[o][s] = tanh( sum_{j<96} A[o][j] * B[j][s] )
//  A: j<32 -> coef[b][o][j] ; j>=32 -> conv_w[l][o][j-32]
//  B: j<32 -> tab[j][s]     ; j>=32 -> h[b][j-32][s]
// block: 64 o x 256 s; 256 threads; thread tile 8 o x 8 s (s = sg*4+c + h*128)
__global__ void __launch_bounds__(256) k_inv(const float* __restrict__ cw, int l,
                                             int cur, int nxt) {
    __shared__ float Ad[96 * 68];   // [j][o]
    __shared__ float Bs[16 * 260];  // [jj][s]
    int t = threadIdx.x;
    int og = t >> 5, sg = t & 31;
    int b = blockIdx.y;
    int s0 = blockIdx.x * 256;
    const float* cf = g_coef + (b * NW) * NC;
    for (int idx = t; idx < 96 * 64; idx += 256) {
        int r = idx >> 6, o = idx & 63;
        Ad[r * 68 + o] = (r < 32) ? cf[o * NC + r]
                                  : cw[(l * NW + o) * NW + (r - 32)];
    }
    unsigned long long acc[8][4];
#pragma unroll
    for (int oo = 0; oo < 8; oo++)
#pragma unroll
        for (int sp = 0; sp < 4; sp++) acc[oo][sp] = 0ull;

    const float* hb = g_h[cur] + (size_t)(b * NW) * NS;
    for (int ch = 0; ch < 6; ch++) {
        __syncthreads();
#pragma unroll
        for (int it = 0; it < 16; it++) {
            int j = ch * 16 + it;
            Bs[it * 260 + t] = (j < 32) ? g_tab[j * NS + s0 + t]
                                        : hb[(size_t)(j - 32) * NS + s0 + t];
        }
        __syncthreads();
#pragma unroll 4
        for (int it = 0; it < 16; it++) {
            int j = ch * 16 + it;
            float4 a0 = *(const float4*)&Ad[j * 68 + og * 8];
            float4 a1 = *(const float4*)&Ad[j * 68 + og * 8 + 4];
            ulonglong2 B0 = *(const ulonglong2*)&Bs[it * 260 + sg * 4];
            ulonglong2 B1 = *(const ulonglong2*)&Bs[it * 260 + 128 + sg * 4];
            unsigned long long ad;
            ad = pk2(a0.x);
            fma2(acc[0][0], ad, B0.x); fma2(acc[0][1], ad, B0.y);
            fma2(acc[0][2], ad, B1.x); fma2(acc[0][3], ad, B1.y);
            ad = pk2(a0.y);
            fma2(acc[1][0], ad, B0.x); fma2(acc[1][1], ad, B0.y);
            fma2(acc[1][2], ad, B1.x); fma2(acc[1][3], ad, B1.y);
            ad = pk2(a0.z);
            fma2(acc[2][0], ad, B0.x); fma2(acc[2][1], ad, B0.y);
            fma2(acc[2][2], ad, B1.x); fma2(acc[2][3], ad, B1.y);
            ad = pk2(a0.w);
            fma2(acc[3][0], ad, B0.x); fma2(acc[3][1], ad, B0.y);
            fma2(acc[3][2], ad, B1.x); fma2(acc[3][3], ad, B1.y);
            ad = pk2(a1.x);
            fma2(acc[4][0], ad, B0.x); fma2(acc[4][1], ad, B0.y);
            fma2(acc[4][2], ad, B1.x); fma2(acc[4][3], ad, B1.y);
            ad = pk2(a1.y);
            fma2(acc[5][0], ad, B0.x); fma2(acc[5][1], ad, B0.y);
            fma2(acc[5][2], ad, B1.x); fma2(acc[5][3], ad, B1.y);
            ad = pk2(a1.z);
            fma2(acc[6][0], ad, B0.x); fma2(acc[6][1], ad, B0.y);
            fma2(acc[6][2], ad, B1.x); fma2(acc[6][3], ad, B1.y);
            ad = pk2(a1.w);
            fma2(acc[7][0], ad, B0.x); fma2(acc[7][1], ad, B0.y);
            fma2(acc[7][2], ad, B1.x); fma2(acc[7][3], ad, B1.y);
        }
    }
    float* dst = g_h[nxt] + (size_t)(b * NW) * NS + s0;
#pragma unroll
    for (int oo = 0; oo < 8; oo++) {
        int o = og * 8 + oo;
        float2 v0 = up2(acc[oo][0]), v1 = up2(acc[oo][1]);
        float2 v2 = up2(acc[oo][2]), v3 = up2(acc[oo][3]);
        float4 w0 = make_float4(ftanh(v0.x), ftanh(v0.y), ftanh(v1.x), ftanh(v1.y));
        float4 w1 = make_float4(ftanh(v2.x), ftanh(v2.y), ftanh(v3.x), ftanh(v3.y));
        *(float4*)&dst[(size_t)o * NS + sg * 4] = w0;
        *(float4*)&dst[(size_t)o * NS + 128 + sg * 4] = w1;
    }
}

// ================= head: q-proj + tanh + output dot =================
__global__ void __launch_bounds__(256) k_head(const float* __restrict__ qw,
                                              const float* __restrict__ qb,
                                              const float* __restrict__ ow,
                                              const float* __restrict__ ob,
                                              float* __restrict__ out, int cur) {
    __shared__ float Aq[64 * 36];   // [i][q]
    __shared__ float Bq[32 * 260];  // rows 0..15: h chunk during GEMM; then qa[32][260]
    int t = threadIdx.x;
    int qg = t >> 5, sg = t & 31;
    int b = blockIdx.y;
    int s0 = blockIdx.x * 256;
    for (int idx = t; idx < 64 * 32; idx += 256) {
        int i = idx >> 5, q = idx & 31;
        Aq[i * 36 + q] = qw[i * 32 + q];
    }
    unsigned long long acc[4][4];
#pragma unroll
    for (int qq = 0; qq < 4; qq++)
#pragma unroll
        for (int sp = 0; sp < 4; sp++) acc[qq][sp] = 0ull;

    const float* hb = g_h[cur] + (size_t)(b * NW) * NS;
    for (int ch = 0; ch < 4; ch++) {
        __syncthreads();
#pragma unroll
        for (int it = 0; it < 16; it++)
            Bq[it * 260 + t] = hb[(size_t)(ch * 16 + it) * NS + s0 + t];
        __syncthreads();
#pragma unroll 4
        for (int it = 0; it < 16; it++) {
            int i = ch * 16 + it;
            float4 a0 = *(const float4*)&Aq[i * 36 + qg * 4];
            ulonglong2 B0 = *(const ulonglong2*)&Bq[it * 260 + sg * 4];
            ulonglong2 B1 = *(const ulonglong2*)&Bq[it * 260 + 128 + sg * 4];
            unsigned long long ad;
            ad = pk2(a0.x);
            fma2(acc[0][0], ad, B0.x); fma2(acc[0][1], ad, B0.y);
            fma2(acc[0][2], ad, B1.x); fma2(acc[0][3], ad, B1.y);
            ad = pk2(a0.y);
            fma2(acc[1][0], ad, B0.x); fma2(acc[1][1], ad, B0.y);
            fma2(acc[1][2], ad, B1.x); fma2(acc[1][3], ad, B1.y);
            ad = pk2(a0.z);
            fma2(acc[2][0], ad, B0.x); fma2(acc[2][1], ad, B0.y);
            fma2(acc[2][2], ad, B1.x); fma2(acc[2][3], ad, B1.y);
            ad = pk2(a0.w);
            fma2(acc[3][0], ad, B0.x); fma2(acc[3][1], ad, B0.y);
            fma2(acc[3][2], ad, B1.x); fma2(acc[3][3], ad, B1.y);
        }
    }
    __syncthreads();   // done reading Bq as h-chunks; reuse as qa
#pragma unroll
    for (int qq = 0; qq < 4; qq++) {
        int q = qg * 4 + qq;
        float qbv = qb[q];
#pragma unroll
        for (int sp = 0; sp < 4; sp++) {
            float2 v = up2(acc[qq][sp]);
            int sl = (sp >> 1) * 128 + sg * 4 + (sp & 1) * 2;
            Bq[q * 260 + sl] = ftanh(v.x + qbv);
            Bq[q * 260 + sl + 1] = ftanh(v.y + qbv);
        }
    }
    __syncthreads();
    float r = ob[0];
#pragma unroll 8
    for (int q = 0; q < 32; q++) r = fmaf(Bq[q * 260 + t], ow[q], r);
    out[(size_t)b * NS + s0 + t] = r;
}

// ================= launcher =================
extern "C" void kernel_launch(void* const* d_in, const int* in_sizes, int n_in,
                              void* d_out, int out_size) {
    const float* x  = (const float*)d_in[0];
    const float* pw = (const float*)d_in[1];
    const float* pb = (const float*)d_in[2];
    const float* wr = (const float*)d_in[3];
    const float* wi = (const float*)d_in[4];
    const float* cw = (const float*)d_in[5];
    const float* cb = (const float*)d_in[6];
    const float* qw = (const float*)d_in[7];
    const float* qb = (const float*)d_in[8];
    const float* ow = (const float*)d_in[9];
    const float* ob = (const float*)d_in[10];
    float* out = (float*)d_out;

    k_tab<<<NS / 256, 256>>>();
    k_lift<<<dim3(NS / 256, NB), 256>>>(x, pw, pb);
    int cur = 0;
    for (int l = 0; l < NL; l++) {
        k_fwd<<<dim3(NSPLIT, NB), 64>>>(cur);
        k_mix<<<NB, 128>>>(wr, wi, cb, l);
        k_inv<<<dim3(NS / 256, NB), 256>>>(cw, l, cur, 1 - cur);
        cur ^= 1;
    }
    k_head<<<dim3(NS / 256, NB), 256>>>(qw, qb, ow, ob, out, cur);
}

// round 3
// speedup vs baseline: 1.2455x; 1.2455x over previous
#include <cuda_runtime.h>
#include <math.h>

#define NB 64
#define NS 8192
#define NW 64
#define NM 16
#define NC 32
#define NL 4
#define NSPLIT 16
#define SCH (NS / NSPLIT)

// ---------------- device scratch (no cudaMalloc allowed) ----------------
__device__ float g_h[2][NB * NW * NS];        // ping-pong activations (b,i,s)
__device__ float g_tab[NC * NS];              // rows 0..15 cos(2pi k s/S), 16..31 sin
__device__ float g_ftp[NSPLIT][NB * NW * NC]; // split-K partial DFT sums
__device__ float g_ft[NB * NW * NC];          // reduced: fr rows 0..15, fi rows 16..31
__device__ float g_coef[NB * NW * NC];        // per (b,o): A(cos) rows 0..15, B(sin) rows 16..31

// ---------------- packed f32x2 helpers ----------------
static __device__ __forceinline__ void fma2(unsigned long long& d,
                                            unsigned long long a,
                                            unsigned long long b) {
    asm("fma.rn.f32x2 %0, %1, %2, %0;" : "+l"(d) : "l"(a), "l"(b));
}
static __device__ __forceinline__ unsigned long long pk2(float v) {
    unsigned long long r;
    asm("mov.b64 %0, {%1, %1};" : "=l"(r) : "f"(v));
    return r;
}
static __device__ __forceinline__ float2 up2(unsigned long long p) {
    float2 r;
    asm("mov.b64 {%0, %1}, %2;" : "=f"(r.x), "=f"(r.y) : "l"(p));
    return r;
}

// fast accurate tanh: 2 MUFU (EX2 + RCP), ~1e-6 abs error, no branches
static __device__ __forceinline__ float ftanh(float x) {
    float ax = fminf(fabsf(x), 10.0f);
    float e = __expf(2.0f * ax);                       // MUFU.EX2 path
    float t = (e - 1.0f) * __fdividef(1.0f, e + 1.0f); // MUFU.RCP path
    return copysignf(t, x);
}

// ================= basis table =================
__global__ void k_tab() {
    int s = blockIdx.x * 256 + threadIdx.x;
    if (s >= NS) return;
#pragma unroll
    for (int k = 0; k < NM; k++) {
        int ph = (k * s) & (NS - 1);
        float ang = (float)((double)ph * (6.283185307179586476925287 / (double)NS));
        float c, sn;
        sincosf(ang, &c, &sn);
        g_tab[k * NS + s] = c;
        g_tab[(k + NM) * NS + s] = sn;
    }
}

// ================= lift =================
__global__ void __launch_bounds__(256) k_lift(const float* __restrict__ x,
                                              const float* __restrict__ pw,
                                              const float* __restrict__ pb) {
    __shared__ float w0[NW], w1[NW], bb[NW];
    int t = threadIdx.x;
    if (t < NW) { w0[t] = pw[t]; w1[t] = pw[NW + t]; bb[t] = pb[t]; }
    __syncthreads();
    int b = blockIdx.y;
    int s = blockIdx.x * 256 + t;
    float2 xv = ((const float2*)x)[b * NS + s];
    float* dst = &g_h[0][(size_t)(b * NW) * NS + s];
#pragma unroll 8
    for (int i = 0; i < NW; i++)
        dst[(size_t)i * NS] = fmaf(xv.x, w0[i], fmaf(xv.y, w1[i], bb[i]));
}

// ================= forward DFT partials =================
// block = (split, b); 64 threads; out C[i][kc] (64x32) over 512-sample chunk.
__global__ void __launch_bounds__(64) k_fwd(int cur) {
    __shared__ float hT[32 * 68];   // [kk][i]
    __shared__ float tt[32 * 36];   // [kk][kc]
    int t = threadIdx.x;
    int ig = t & 7, kg = t >> 3;
    int b = blockIdx.y;
    int s0 = blockIdx.x * SCH;
    const float* hb = g_h[cur] + (size_t)(b * NW) * NS;

    unsigned long long acc[2][2][4];
#pragma unroll
    for (int h = 0; h < 2; h++)
#pragma unroll
        for (int p = 0; p < 2; p++)
#pragma unroll
            for (int k = 0; k < 4; k++) acc[h][p][k] = 0ull;

    for (int ts = 0; ts < SCH; ts += 32) {
#pragma unroll
        for (int j = 0; j < 32; j++) {
            int idx = j * 64 + t;
            int i = idx >> 5, kk = idx & 31;
            hT[kk * 68 + i] = hb[(size_t)i * NS + s0 + ts + kk];
        }
#pragma unroll
        for (int j = 0; j < 16; j++) {
            int idx = j * 64 + t;
            int k = idx >> 5, kk = idx & 31;
            tt[kk * 36 + k] = g_tab[k * NS + s0 + ts + kk];
        }
        __syncthreads();
#pragma unroll 8
        for (int kk = 0; kk < 32; kk++) {
            ulonglong2 A0 = *(const ulonglong2*)&hT[kk * 68 + ig * 4];
            ulonglong2 A1 = *(const ulonglong2*)&hT[kk * 68 + 32 + ig * 4];
            float4 bv = *(const float4*)&tt[kk * 36 + kg * 4];
            unsigned long long b0 = pk2(bv.x), b1 = pk2(bv.y),
                               b2 = pk2(bv.z), b3 = pk2(bv.w);
            fma2(acc[0][0][0], A0.x, b0); fma2(acc[0][0][1], A0.x, b1);
            fma2(acc[0][0][2], A0.x, b2); fma2(acc[0][0][3], A0.x, b3);
            fma2(acc[0][1][0], A0.y, b0); fma2(acc[0][1][1], A0.y, b1);
            fma2(acc[0][1][2], A0.y, b2); fma2(acc[0][1][3], A0.y, b3);
            fma2(acc[1][0][0], A1.x, b0); fma2(acc[1][0][1], A1.x, b1);
            fma2(acc[1][0][2], A1.x, b2); fma2(acc[1][0][3], A1.x, b3);
            fma2(acc[1][1][0], A1.y, b0); fma2(acc[1][1][1], A1.y, b1);
            fma2(acc[1][1][2], A1.y, b2); fma2(acc[1][1][3], A1.y, b3);
        }
        __syncthreads();
    }
    float* fp = g_ftp[blockIdx.x] + (b * NW) * NC;
#pragma unroll
    for (int h = 0; h < 2; h++)
#pragma unroll
        for (int p = 0; p < 2; p++)
#pragma unroll
            for (int k = 0; k < 4; k++) {
                int i = h * 32 + ig * 4 + p * 2;
                float2 v = up2(acc[h][p][k]);
                fp[i * NC + kg * 4 + k] = v.x;
                fp[(i + 1) * NC + kg * 4 + k] = v.y;
            }
}

// ================= split-K reduce (coalesced) =================
__global__ void __launch_bounds__(256) k_red() {
    int idx = blockIdx.x * 256 + threadIdx.x;
    float v = 0.f;
#pragma unroll
    for (int sp = 0; sp < NSPLIT; sp++) v += g_ftp[sp][idx];
    int kc = idx & 31;
    // fr = +cos-sum/S in rows 0..15 ; fi = -sin-sum/S in rows 16..31
    g_ft[idx] = (kc < NM ? v : -v) * (1.0f / NS);
}

// ================= mode mix (smem-tiled weights) =================
// block = (mode k, batch-group bg of 16); weights slice + F staged in smem.
__global__ void __launch_bounds__(256) k_mix2(const float* __restrict__ wr,
                                              const float* __restrict__ wi,
                                              const float* __restrict__ cb, int l) {
    __shared__ float wrs[64 * 65], wis[64 * 65];
    __shared__ float frs[16 * 64], fis[16 * 64];
    int t = threadIdx.x;
    int k = blockIdx.x, bg = blockIdx.y;
    const float* wrl = wr + (size_t)l * NW * NW * NM;
    const float* wil = wi + (size_t)l * NW * NW * NM;
    for (int idx = t; idx < 4096; idx += 256) {
        int i = idx >> 6, o = idx & 63;
        wrs[i * 65 + o] = wrl[(i * 64 + o) * NM + k];
        wis[i * 65 + o] = wil[(i * 64 + o) * NM + k];
    }
    for (int idx = t; idx < 1024; idx += 256) {
        int b16 = idx >> 6, i = idx & 63;
        int b = bg * 16 + b16;
        frs[b16 * 64 + i] = g_ft[(b * NW + i) * NC + k];
        fis[b16 * 64 + i] = g_ft[(b * NW + i) * NC + NM + k];
    }
    __syncthreads();
#pragma unroll
    for (int u = 0; u < 4; u++) {
        int oi = t + u * 256;
        int o = oi & 63, b16 = oi >> 6;
        float sr = 0.f, si = 0.f;
#pragma unroll 8
        for (int i = 0; i < 64; i++) {
            float fr = frs[b16 * 64 + i], fi = fis[b16 * 64 + i];
            float a = wrs[i * 65 + o], c = wis[i * 65 + o];
            sr = fmaf(fr, a, sr); sr = fmaf(-fi, c, sr);
            si = fmaf(fr, c, si); si = fmaf(fi, a, si);
        }
        int b = bg * 16 + b16;
        float* cf = g_coef + (b * NW + o) * NC;
        if (k == 0) { cf[0] = sr + cb[l * NW + o]; cf[NM] = 0.f; }
        else        { cf[k] = 2.f * sr; cf[NM + k] = -2.f * si; }
    }
}

// ================= fused irfft + 1x1 conv + tanh =================
__global__ void __launch_bounds__(256) k_inv(const float* __restrict__ cw, int l,
                                             int cur, int nxt) {
    __shared__ float Ad[96 * 68];   // [j][o]
    __shared__ float Bs[16 * 260];  // [jj][s]
    int t = threadIdx.x;
    int og = t >> 5, sg = t & 31;
    int b = blockIdx.y;
    int s0 = blockIdx.x * 256;
    const float* cf = g_coef + (b * NW) * NC;
    for (int idx = t; idx < 96 * 64; idx += 256) {
        int r = idx >> 6, o = idx & 63;
        Ad[r * 68 + o] = (r < 32) ? cf[o * NC + r]
                                  : cw[(l * NW + o) * NW + (r - 32)];
    }
    unsigned long long acc[8][4];
#pragma unroll
    for (int oo = 0; oo < 8; oo++)
#pragma unroll
        for (int sp = 0; sp < 4; sp++) acc[oo][sp] = 0ull;

    const float* hb = g_h[cur] + (size_t)(b * NW) * NS;
    for (int ch = 0; ch < 6; ch++) {
        __syncthreads();
#pragma unroll
        for (int it = 0; it < 16; it++) {
            int j = ch * 16 + it;
            Bs[it * 260 + t] = (j < 32) ? g_tab[j * NS + s0 + t]
                                        : hb[(size_t)(j - 32) * NS + s0 + t];
        }
        __syncthreads();
#pragma unroll 4
        for (int it = 0; it < 16; it++) {
            int j = ch * 16 + it;
            float4 a0 = *(const float4*)&Ad[j * 68 + og * 8];
            float4 a1 = *(const float4*)&Ad[j * 68 + og * 8 + 4];
            ulonglong2 B0 = *(const ulonglong2*)&Bs[it * 260 + sg * 4];
            ulonglong2 B1 = *(const ulonglong2*)&Bs[it * 260 + 128 + sg * 4];
            unsigned long long ad;
            ad = pk2(a0.x);
            fma2(acc[0][0], ad, B0.x); fma2(acc[0][1], ad, B0.y);
            fma2(acc[0][2], ad, B1.x); fma2(acc[0][3], ad, B1.y);
            ad = pk2(a0.y);
            fma2(acc[1][0], ad, B0.x); fma2(acc[1][1], ad, B0.y);
            fma2(acc[1][2], ad, B1.x); fma2(acc[1][3], ad, B1.y);
            ad = pk2(a0.z);
            fma2(acc[2][0], ad, B0.x); fma2(acc[2][1], ad, B0.y);
            fma2(acc[2][2], ad, B1.x); fma2(acc[2][3], ad, B1.y);
            ad = pk2(a0.w);
            fma2(acc[3][0], ad, B0.x); fma2(acc[3][1], ad, B0.y);
            fma2(acc[3][2], ad, B1.x); fma2(acc[3][3], ad, B1.y);
            ad = pk2(a1.x);
            fma2(acc[4][0], ad, B0.x); fma2(acc[4][1], ad, B0.y);
            fma2(acc[4][2], ad, B1.x); fma2(acc[4][3], ad, B1.y);
            ad = pk2(a1.y);
            fma2(acc[5][0], ad, B0.x); fma2(acc[5][1], ad, B0.y);
            fma2(acc[5][2], ad, B1.x); fma2(acc[5][3], ad, B1.y);
            ad = pk2(a1.z);
            fma2(acc[6][0], ad, B0.x); fma2(acc[6][1], ad, B0.y);
            fma2(acc[6][2], ad, B1.x); fma2(acc[6][3], ad, B1.y);
            ad = pk2(a1.w);
            fma2(acc[7][0], ad, B0.x); fma2(acc[7][1], ad, B0.y);
            fma2(acc[7][2], ad, B1.x); fma2(acc[7][3], ad, B1.y);
        }
    }
    float* dst = g_h[nxt] + (size_t)(b * NW) * NS + s0;
#pragma unroll
    for (int oo = 0; oo < 8; oo++) {
        int o = og * 8 + oo;
        float2 v0 = up2(acc[oo][0]), v1 = up2(acc[oo][1]);
        float2 v2 = up2(acc[oo][2]), v3 = up2(acc[oo][3]);
        float4 w0 = make_float4(ftanh(v0.x), ftanh(v0.y), ftanh(v1.x), ftanh(v1.y));
        float4 w1 = make_float4(ftanh(v2.x), ftanh(v2.y), ftanh(v3.x), ftanh(v3.y));
        *(float4*)&dst[(size_t)o * NS + sg * 4] = w0;
        *(float4*)&dst[(size_t)o * NS + 128 + sg * 4] = w1;
    }
}

// ================= head: q-proj + tanh + output dot =================
__global__ void __launch_bounds__(256) k_head(const float* __restrict__ qw,
                                              const float* __restrict__ qb,
                                              const float* __restrict__ ow,
                                              const float* __restrict__ ob,
                                              float* __restrict__ out, int cur) {
    __shared__ float Aq[64 * 36];
    __shared__ float Bq[32 * 260];
    int t = threadIdx.x;
    int qg = t >> 5, sg = t & 31;
    int b = blockIdx.y;
    int s0 = blockIdx.x * 256;
    for (int idx = t; idx < 64 * 32; idx += 256) {
        int i = idx >> 5, q = idx & 31;
        Aq[i * 36 + q] = qw[i * 32 + q];
    }
    unsigned long long acc[4][4];
#pragma unroll
    for (int qq = 0; qq < 4; qq++)
#pragma unroll
        for (int sp = 0; sp < 4; sp++) acc[qq][sp] = 0ull;

    const float* hb = g_h[cur] + (size_t)(b * NW) * NS;
    for (int ch = 0; ch < 4; ch++) {
        __syncthreads();
#pragma unroll
        for (int it = 0; it < 16; it++)
            Bq[it * 260 + t] = hb[(size_t)(ch * 16 + it) * NS + s0 + t];
        __syncthreads();
#pragma unroll 4
        for (int it = 0; it < 16; it++) {
            int i = ch * 16 + it;
            float4 a0 = *(const float4*)&Aq[i * 36 + qg * 4];
            ulonglong2 B0 = *(const ulonglong2*)&Bq[it * 260 + sg * 4];
            ulonglong2 B1 = *(const ulonglong2*)&Bq[it * 260 + 128 + sg * 4];
            unsigned long long ad;
            ad = pk2(a0.x);
            fma2(acc[0][0], ad, B0.x); fma2(acc[0][1], ad, B0.y);
            fma2(acc[0][2], ad, B1.x); fma2(acc[0][3], ad, B1.y);
            ad = pk2(a0.y);
            fma2(acc[1][0], ad, B0.x); fma2(acc[1][1], ad, B0.y);
            fma2(acc[1][2], ad, B1.x); fma2(acc[1][3], ad, B1.y);
            ad = pk2(a0.z);
            fma2(acc[2][0], ad, B0.x); fma2(acc[2][1], ad, B0.y);
            fma2(acc[2][2], ad, B1.x); fma2(acc[2][3], ad, B1.y);
            ad = pk2(a0.w);
            fma2(acc[3][0], ad, B0.x); fma2(acc[3][1], ad, B0.y);
            fma2(acc[3][2], ad, B1.x); fma2(acc[3][3], ad, B1.y);
        }
    }
    __syncthreads();
#pragma unroll
    for (int qq = 0; qq < 4; qq++) {
        int q = qg * 4 + qq;
        float qbv = qb[q];
#pragma unroll
        for (int sp = 0; sp < 4; sp++) {
            float2 v = up2(acc[qq][sp]);
            int sl = (sp >> 1) * 128 + sg * 4 + (sp & 1) * 2;
            Bq[q * 260 + sl] = ftanh(v.x + qbv);
            Bq[q * 260 + sl + 1] = ftanh(v.y + qbv);
        }
    }
    __syncthreads();
    float r = ob[0];
#pragma unroll 8
    for (int q = 0; q < 32; q++) r = fmaf(Bq[q * 260 + t], ow[q], r);
    out[(size_t)b * NS + s0 + t] = r;
}

// ================= launcher =================
extern "C" void kernel_launch(void* const* d_in, const int* in_sizes, int n_in,
                              void* d_out, int out_size) {
    const float* x  = (const float*)d_in[0];
    const float* pw = (const float*)d_in[1];
    const float* pb = (const float*)d_in[2];
    const float* wr = (const float*)d_in[3];
    const float* wi = (const float*)d_in[4];
    const float* cw = (const float*)d_in[5];
    const float* cb = (const float*)d_in[6];
    const float* qw = (const float*)d_in[7];
    const float* qb = (const float*)d_in[8];
    const float* ow = (const float*)d_in[9];
    const float* ob = (const float*)d_in[10];
    float* out = (float*)d_out;

    k_tab<<<NS / 256, 256>>>();
    k_lift<<<dim3(NS / 256, NB), 256>>>(x, pw, pb);
    int cur = 0;
    for (int l = 0; l < NL; l++) {
        k_fwd<<<dim3(NSPLIT, NB), 64>>>(cur);
        k_red<<<(NB * NW * NC) / 256, 256>>>();
        k_mix2<<<dim3(NM, 4), 256>>>(wr, wi, cb, l);
        k_inv<<<dim3(NS / 256, NB), 256>>>(cw, l, cur, 1 - cur);
        cur ^= 1;
    }
    k_head<<<dim3(NS / 256, NB), 256>>>(qw, qb, ow, ob, out, cur);
}

// round 4
// speedup vs baseline: 1.3842x; 1.1114x over previous
#include <cuda_runtime.h>
#include <math.h>

#define NB 64
#define NS 8192
#define NW 64
#define NM 16
#define NC 32
#define NL 4
#define NSPLIT 16
#define SCH (NS / NSPLIT)

// ---------------- device scratch (no cudaMalloc allowed) ----------------
__device__ float g_h[2][NB * NW * NS];        // ping-pong activations (b,i,s)
__device__ float g_tab[NC * NS];              // rows 0..15 cos(2pi k s/S), 16..31 sin
__device__ float g_ftp[NSPLIT][NB * NW * NC]; // split-K partial DFT sums
__device__ float g_ft[NB * NW * NC];          // reduced: fr rows 0..15, fi rows 16..31
__device__ float g_coef[NB * NW * NC];        // per (b,o): A(cos) 0..15, B(sin) 16..31
__device__ float g_xft[NB * 2 * NC];          // DFT of x channels (fr/fi convention)
__device__ float g_cw0[2 * NW];               // conv_w[0] @ p_w^T  : [c][o]
__device__ float g_b0[NW];                    // conv_w[0] @ p_b    : [o]

// ---------------- packed f32x2 helpers ----------------
static __device__ __forceinline__ void fma2(unsigned long long& d,
                                            unsigned long long a,
                                            unsigned long long b) {
    asm("fma.rn.f32x2 %0, %1, %2, %0;" : "+l"(d) : "l"(a), "l"(b));
}
static __device__ __forceinline__ unsigned long long pk2(float v) {
    unsigned long long r;
    asm("mov.b64 %0, {%1, %1};" : "=l"(r) : "f"(v));
    return r;
}
static __device__ __forceinline__ float2 up2(unsigned long long p) {
    float2 r;
    asm("mov.b64 {%0, %1}, %2;" : "=f"(r.x), "=f"(r.y) : "l"(p));
    return r;
}

// fast accurate tanh: 2 MUFU (EX2 + RCP), ~1e-6 abs error
static __device__ __forceinline__ float ftanh(float x) {
    float ax = fminf(fabsf(x), 10.0f);
    float e = __expf(2.0f * ax);
    float t = (e - 1.0f) * __fdividef(1.0f, e + 1.0f);
    return copysignf(t, x);
}

// ================= basis table =================
__global__ void k_tab() {
    int s = blockIdx.x * 256 + threadIdx.x;
    if (s >= NS) return;
#pragma unroll
    for (int k = 0; k < NM; k++) {
        int ph = (k * s) & (NS - 1);
        float ang = (float)((double)ph * (6.283185307179586476925287 / (double)NS));
        float c, sn;
        sincosf(ang, &c, &sn);
        g_tab[k * NS + s] = c;
        g_tab[(k + NM) * NS + s] = sn;
    }
}

// ================= layer-0 folded weights =================
// g_cw0[c][o] = sum_i conv_w[0][o][i] * p_w[c][i] ; g_b0[o] = conv_w[0][o] . p_b
__global__ void k_prep(const float* __restrict__ cw, const float* __restrict__ pw,
                       const float* __restrict__ pb) {
    int o = threadIdx.x;
    if (o >= NW) return;
    float c0 = 0.f, c1 = 0.f, bv = 0.f;
#pragma unroll 8
    for (int i = 0; i < NW; i++) {
        float w = cw[o * NW + i];
        c0 = fmaf(w, pw[i], c0);
        c1 = fmaf(w, pw[NW + i], c1);
        bv = fmaf(w, pb[i], bv);
    }
    g_cw0[o] = c0;
    g_cw0[NW + o] = c1;
    g_b0[o] = bv;
}

// ================= DFT of raw input x (2 channels) =================
// g_xft[(b*2+c)*NC+kc] : kc<16 -> +cos-sum/S ; kc>=16 -> -sin-sum/S
__global__ void __launch_bounds__(256) k_xdft(const float* __restrict__ x) {
    int t = threadIdx.x;
    int w = t >> 5, lane = t & 31;
    int b = blockIdx.x;
    const float2* x2 = (const float2*)x + (size_t)b * NS;
    int k0 = w * 4;                 // this warp: kc rows k0..k0+3 (cos/sin per index)
    float acc[2][4];
#pragma unroll
    for (int c = 0; c < 2; c++)
#pragma unroll
        for (int k = 0; k < 4; k++) acc[c][k] = 0.f;
    for (int s = lane; s < NS; s += 32) {
        float2 xv = x2[s];
#pragma unroll
        for (int k = 0; k < 4; k++) {
            float tv = g_tab[(k0 + k) * NS + s];
            acc[0][k] = fmaf(xv.x, tv, acc[0][k]);
            acc[1][k] = fmaf(xv.y, tv, acc[1][k]);
        }
    }
#pragma unroll
    for (int off = 16; off > 0; off >>= 1)
#pragma unroll
        for (int c = 0; c < 2; c++)
#pragma unroll
            for (int k = 0; k < 4; k++)
                acc[c][k] += __shfl_xor_sync(0xffffffffu, acc[c][k], off);
    if (lane == 0) {
#pragma unroll
        for (int c = 0; c < 2; c++)
#pragma unroll
            for (int k = 0; k < 4; k++) {
                int kc = k0 + k;
                float v = acc[c][k] * (1.0f / NS);
                g_xft[(b * 2 + c) * NC + kc] = (kc < NM) ? v : -v;
            }
    }
}

// ================= layer-0 spectrum: g_ft = pw^T (x-spectrum) + pb delta =================
__global__ void __launch_bounds__(256) k_ft0(const float* __restrict__ pw,
                                             const float* __restrict__ pb) {
    int idx = blockIdx.x * 256 + threadIdx.x;   // (b*NW+i)*NC+kc
    int kc = idx & 31;
    int bi = idx >> 5;
    int i = bi & 63, b = bi >> 6;
    float v = pw[i] * g_xft[(b * 2 + 0) * NC + kc]
            + pw[NW + i] * g_xft[(b * 2 + 1) * NC + kc];
    if (kc == 0) v += pb[i];
    g_ft[idx] = v;
}

// ================= forward DFT partials (layers >= 1) =================
__global__ void __launch_bounds__(64) k_fwd(int cur) {
    __shared__ float hT[32 * 68];
    __shared__ float tt[32 * 36];
    int t = threadIdx.x;
    int ig = t & 7, kg = t >> 3;
    int b = blockIdx.y;
    int s0 = blockIdx.x * SCH;
    const float* hb = g_h[cur] + (size_t)(b * NW) * NS;

    unsigned long long acc[2][2][4];
#pragma unroll
    for (int h = 0; h < 2; h++)
#pragma unroll
        for (int p = 0; p < 2; p++)
#pragma unroll
            for (int k = 0; k < 4; k++) acc[h][p][k] = 0ull;

    for (int ts = 0; ts < SCH; ts += 32) {
#pragma unroll
        for (int j = 0; j < 32; j++) {
            int idx = j * 64 + t;
            int i = idx >> 5, kk = idx & 31;
            hT[kk * 68 + i] = hb[(size_t)i * NS + s0 + ts + kk];
        }
#pragma unroll
        for (int j = 0; j < 16; j++) {
            int idx = j * 64 + t;
            int k = idx >> 5, kk = idx & 31;
            tt[kk * 36 + k] = g_tab[k * NS + s0 + ts + kk];
        }
        __syncthreads();
#pragma unroll 8
        for (int kk = 0; kk < 32; kk++) {
            ulonglong2 A0 = *(const ulonglong2*)&hT[kk * 68 + ig * 4];
            ulonglong2 A1 = *(const ulonglong2*)&hT[kk * 68 + 32 + ig * 4];
            float4 bv = *(const float4*)&tt[kk * 36 + kg * 4];
            unsigned long long b0 = pk2(bv.x), b1 = pk2(bv.y),
                               b2 = pk2(bv.z), b3 = pk2(bv.w);
            fma2(acc[0][0][0], A0.x, b0); fma2(acc[0][0][1], A0.x, b1);
            fma2(acc[0][0][2], A0.x, b2); fma2(acc[0][0][3], A0.x, b3);
            fma2(acc[0][1][0], A0.y, b0); fma2(acc[0][1][1], A0.y, b1);
            fma2(acc[0][1][2], A0.y, b2); fma2(acc[0][1][3], A0.y, b3);
            fma2(acc[1][0][0], A1.x, b0); fma2(acc[1][0][1], A1.x, b1);
            fma2(acc[1][0][2], A1.x, b2); fma2(acc[1][0][3], A1.x, b3);
            fma2(acc[1][1][0], A1.y, b0); fma2(acc[1][1][1], A1.y, b1);
            fma2(acc[1][1][2], A1.y, b2); fma2(acc[1][1][3], A1.y, b3);
        }
        __syncthreads();
    }
    float* fp = g_ftp[blockIdx.x] + (b * NW) * NC;
#pragma unroll
    for (int h = 0; h < 2; h++)
#pragma unroll
        for (int p = 0; p < 2; p++)
#pragma unroll
            for (int k = 0; k < 4; k++) {
                int i = h * 32 + ig * 4 + p * 2;
                float2 v = up2(acc[h][p][k]);
                fp[i * NC + kg * 4 + k] = v.x;
                fp[(i + 1) * NC + kg * 4 + k] = v.y;
            }
}

// ================= split-K reduce =================
__global__ void __launch_bounds__(256) k_red() {
    int idx = blockIdx.x * 256 + threadIdx.x;
    float v = 0.f;
#pragma unroll
    for (int sp = 0; sp < NSPLIT; sp++) v += g_ftp[sp][idx];
    int kc = idx & 31;
    g_ft[idx] = (kc < NM ? v : -v) * (1.0f / NS);
}

// ================= mode mix =================
__global__ void __launch_bounds__(256) k_mix2(const float* __restrict__ wr,
                                              const float* __restrict__ wi,
                                              const float* __restrict__ cb, int l) {
    __shared__ float wrs[64 * 65], wis[64 * 65];
    __shared__ float frs[16 * 64], fis[16 * 64];
    int t = threadIdx.x;
    int k = blockIdx.x, bg = blockIdx.y;
    const float* wrl = wr + (size_t)l * NW * NW * NM;
    const float* wil = wi + (size_t)l * NW * NW * NM;
    for (int idx = t; idx < 4096; idx += 256) {
        int i = idx >> 6, o = idx & 63;
        wrs[i * 65 + o] = wrl[(i * 64 + o) * NM + k];
        wis[i * 65 + o] = wil[(i * 64 + o) * NM + k];
    }
    for (int idx = t; idx < 1024; idx += 256) {
        int b16 = idx >> 6, i = idx & 63;
        int b = bg * 16 + b16;
        frs[b16 * 64 + i] = g_ft[(b * NW + i) * NC + k];
        fis[b16 * 64 + i] = g_ft[(b * NW + i) * NC + NM + k];
    }
    __syncthreads();
#pragma unroll
    for (int u = 0; u < 4; u++) {
        int oi = t + u * 256;
        int o = oi & 63, b16 = oi >> 6;
        float sr = 0.f, si = 0.f;
#pragma unroll 8
        for (int i = 0; i < 64; i++) {
            float fr = frs[b16 * 64 + i], fi = fis[b16 * 64 + i];
            float a = wrs[i * 65 + o], c = wis[i * 65 + o];
            sr = fmaf(fr, a, sr); sr = fmaf(-fi, c, sr);
            si = fmaf(fr, c, si); si = fmaf(fi, a, si);
        }
        int b = bg * 16 + b16;
        float* cf = g_coef + (b * NW + o) * NC;
        if (k == 0) {
            float base = sr + cb[l * NW + o];
            if (l == 0) base += g_b0[o];
            cf[0] = base; cf[NM] = 0.f;
        } else { cf[k] = 2.f * sr; cf[NM + k] = -2.f * si; }
    }
}

// ================= fused irfft + conv + tanh (layers >= 1) =================
__global__ void __launch_bounds__(256) k_inv(const float* __restrict__ cw, int l,
                                             int cur, int nxt) {
    __shared__ float Ad[96 * 68];
    __shared__ float Bs[16 * 260];
    int t = threadIdx.x;
    int og = t >> 5, sg = t & 31;
    int b = blockIdx.y;
    int s0 = blockIdx.x * 256;
    const float* cf = g_coef + (b * NW) * NC;
    for (int idx = t; idx < 96 * 64; idx += 256) {
        int r = idx >> 6, o = idx & 63;
        Ad[r * 68 + o] = (r < 32) ? cf[o * NC + r]
                                  : cw[(l * NW + o) * NW + (r - 32)];
    }
    unsigned long long acc[8][4];
#pragma unroll
    for (int oo = 0; oo < 8; oo++)
#pragma unroll
        for (int sp = 0; sp < 4; sp++) acc[oo][sp] = 0ull;

    const float* hb = g_h[cur] + (size_t)(b * NW) * NS;
    for (int ch = 0; ch < 6; ch++) {
        __syncthreads();
#pragma unroll
        for (int it = 0; it < 16; it++) {
            int j = ch * 16 + it;
            Bs[it * 260 + t] = (j < 32) ? g_tab[j * NS + s0 + t]
                                        : hb[(size_t)(j - 32) * NS + s0 + t];
        }
        __syncthreads();
#pragma unroll 4
        for (int it = 0; it < 16; it++) {
            int j = ch * 16 + it;
            float4 a0 = *(const float4*)&Ad[j * 68 + og * 8];
            float4 a1 = *(const float4*)&Ad[j * 68 + og * 8 + 4];
            ulonglong2 B0 = *(const ulonglong2*)&Bs[it * 260 + sg * 4];
            ulonglong2 B1 = *(const ulonglong2*)&Bs[it * 260 + 128 + sg * 4];
            unsigned long long ad;
            ad = pk2(a0.x);
            fma2(acc[0][0], ad, B0.x); fma2(acc[0][1], ad, B0.y);
            fma2(acc[0][2], ad, B1.x); fma2(acc[0][3], ad, B1.y);
            ad = pk2(a0.y);
            fma2(acc[1][0], ad, B0.x); fma2(acc[1][1], ad, B0.y);
            fma2(acc[1][2], ad, B1.x); fma2(acc[1][3], ad, B1.y);
            ad = pk2(a0.z);
            fma2(acc[2][0], ad, B0.x); fma2(acc[2][1], ad, B0.y);
            fma2(acc[2][2], ad, B1.x); fma2(acc[2][3], ad, B1.y);
            ad = pk2(a0.w);
            fma2(acc[3][0], ad, B0.x); fma2(acc[3][1], ad, B0.y);
            fma2(acc[3][2], ad, B1.x); fma2(acc[3][3], ad, B1.y);
            ad = pk2(a1.x);
            fma2(acc[4][0], ad, B0.x); fma2(acc[4][1], ad, B0.y);
            fma2(acc[4][2], ad, B1.x); fma2(acc[4][3], ad, B1.y);
            ad = pk2(a1.y);
            fma2(acc[5][0], ad, B0.x); fma2(acc[5][1], ad, B0.y);
            fma2(acc[5][2], ad, B1.x); fma2(acc[5][3], ad, B1.y);
            ad = pk2(a1.z);
            fma2(acc[6][0], ad, B0.x); fma2(acc[6][1], ad, B0.y);
            fma2(acc[6][2], ad, B1.x); fma2(acc[6][3], ad, B1.y);
            ad = pk2(a1.w);
            fma2(acc[7][0], ad, B0.x); fma2(acc[7][1], ad, B0.y);
            fma2(acc[7][2], ad, B1.x); fma2(acc[7][3], ad, B1.y);
        }
    }
    float* dst = g_h[nxt] + (size_t)(b * NW) * NS + s0;
#pragma unroll
    for (int oo = 0; oo < 8; oo++) {
        int o = og * 8 + oo;
        float2 v0 = up2(acc[oo][0]), v1 = up2(acc[oo][1]);
        float2 v2 = up2(acc[oo][2]), v3 = up2(acc[oo][3]);
        float4 w0 = make_float4(ftanh(v0.x), ftanh(v0.y), ftanh(v1.x), ftanh(v1.y));
        float4 w1 = make_float4(ftanh(v2.x), ftanh(v2.y), ftanh(v3.x), ftanh(v3.y));
        *(float4*)&dst[(size_t)o * NS + sg * 4] = w0;
        *(float4*)&dst[(size_t)o * NS + 128 + sg * 4] = w1;
    }
}

// ================= layer-0 fused inverse: K = 32 basis + 2 x channels =================
__global__ void __launch_bounds__(256) k_inv0(const float* __restrict__ x, int nxt) {
    __shared__ float Ad[34 * 68];
    __shared__ float Bs[16 * 260];
    int t = threadIdx.x;
    int og = t >> 5, sg = t & 31;
    int b = blockIdx.y;
    int s0 = blockIdx.x * 256;
    const float* cf = g_coef + (b * NW) * NC;
    for (int idx = t; idx < 34 * 64; idx += 256) {
        int r = idx >> 6, o = idx & 63;
        Ad[r * 68 + o] = (r < 32) ? cf[o * NC + r] : g_cw0[(r - 32) * NW + o];
    }
    unsigned long long acc[8][4];
#pragma unroll
    for (int oo = 0; oo < 8; oo++)
#pragma unroll
        for (int sp = 0; sp < 4; sp++) acc[oo][sp] = 0ull;

    for (int ch = 0; ch < 2; ch++) {
        __syncthreads();
#pragma unroll
        for (int it = 0; it < 16; it++) {
            int j = ch * 16 + it;
            Bs[it * 260 + t] = g_tab[j * NS + s0 + t];
        }
        __syncthreads();
#pragma unroll 4
        for (int it = 0; it < 16; it++) {
            int j = ch * 16 + it;
            float4 a0 = *(const float4*)&Ad[j * 68 + og * 8];
            float4 a1 = *(const float4*)&Ad[j * 68 + og * 8 + 4];
            ulonglong2 B0 = *(const ulonglong2*)&Bs[it * 260 + sg * 4];
            ulonglong2 B1 = *(const ulonglong2*)&Bs[it * 260 + 128 + sg * 4];
            unsigned long long ad;
            ad = pk2(a0.x);
            fma2(acc[0][0], ad, B0.x); fma2(acc[0][1], ad, B0.y);
            fma2(acc[0][2], ad, B1.x); fma2(acc[0][3], ad, B1.y);
            ad = pk2(a0.y);
            fma2(acc[1][0], ad, B0.x); fma2(acc[1][1], ad, B0.y);
            fma2(acc[1][2], ad, B1.x); fma2(acc[1][3], ad, B1.y);
            ad = pk2(a0.z);
            fma2(acc[2][0], ad, B0.x); fma2(acc[2][1], ad, B0.y);
            fma2(acc[2][2], ad, B1.x); fma2(acc[2][3], ad, B1.y);
            ad = pk2(a0.w);
            fma2(acc[3][0], ad, B0.x); fma2(acc[3][1], ad, B0.y);
            fma2(acc[3][2], ad, B1.x); fma2(acc[3][3], ad, B1.y);
            ad = pk2(a1.x);
            fma2(acc[4][0], ad, B0.x); fma2(acc[4][1], ad, B0.y);
            fma2(acc[4][2], ad, B1.x); fma2(acc[4][3], ad, B1.y);
            ad = pk2(a1.y);
            fma2(acc[5][0], ad, B0.x); fma2(acc[5][1], ad, B0.y);
            fma2(acc[5][2], ad, B1.x); fma2(acc[5][3], ad, B1.y);
            ad = pk2(a1.z);
            fma2(acc[6][0], ad, B0.x); fma2(acc[6][1], ad, B0.y);
            fma2(acc[6][2], ad, B1.x); fma2(acc[6][3], ad, B1.y);
            ad = pk2(a1.w);
            fma2(acc[7][0], ad, B0.x); fma2(acc[7][1], ad, B0.y);
            fma2(acc[7][2], ad, B1.x); fma2(acc[7][3], ad, B1.y);
        }
    }
    // x-channel mini chunk (rows 32..33), interleaved (B,S,2) source
    __syncthreads();
    {
        const float2* x2 = (const float2*)x + (size_t)b * NS + s0;
        float2 xv = x2[t];
        Bs[0 * 260 + t] = xv.x;
        Bs[1 * 260 + t] = xv.y;
    }
    __syncthreads();
#pragma unroll
    for (int it = 0; it < 2; it++) {
        int j = 32 + it;
        float4 a0 = *(const float4*)&Ad[j * 68 + og * 8];
        float4 a1 = *(const float4*)&Ad[j * 68 + og * 8 + 4];
        ulonglong2 B0 = *(const ulonglong2*)&Bs[it * 260 + sg * 4];
        ulonglong2 B1 = *(const ulonglong2*)&Bs[it * 260 + 128 + sg * 4];
        unsigned long long ad;
        ad = pk2(a0.x);
        fma2(acc[0][0], ad, B0.x); fma2(acc[0][1], ad, B0.y);
        fma2(acc[0][2], ad, B1.x); fma2(acc[0][3], ad, B1.y);
        ad = pk2(a0.y);
        fma2(acc[1][0], ad, B0.x); fma2(acc[1][1], ad, B0.y);
        fma2(acc[1][2], ad, B1.x); fma2(acc[1][3], ad, B1.y);
        ad = pk2(a0.z);
        fma2(acc[2][0], ad, B0.x); fma2(acc[2][1], ad, B0.y);
        fma2(acc[2][2], ad, B1.x); fma2(acc[2][3], ad, B1.y);
        ad = pk2(a0.w);
        fma2(acc[3][0], ad, B0.x); fma2(acc[3][1], ad, B0.y);
        fma2(acc[3][2], ad, B1.x); fma2(acc[3][3], ad, B1.y);
        ad = pk2(a1.x);
        fma2(acc[4][0], ad, B0.x); fma2(acc[4][1], ad, B0.y);
        fma2(acc[4][2], ad, B1.x); fma2(acc[4][3], ad, B1.y);
        ad = pk2(a1.y);
        fma2(acc[5][0], ad, B0.x); fma2(acc[5][1], ad, B0.y);
        fma2(acc[5][2], ad, B1.x); fma2(acc[5][3], ad, B1.y);
        ad = pk2(a1.z);
        fma2(acc[6][0], ad, B0.x); fma2(acc[6][1], ad, B0.y);
        fma2(acc[6][2], ad, B1.x); fma2(acc[6][3], ad, B1.y);
        ad = pk2(a1.w);
        fma2(acc[7][0], ad, B0.x); fma2(acc[7][1], ad, B0.y);
        fma2(acc[7][2], ad, B1.x); fma2(acc[7][3], ad, B1.y);
    }
    float* dst = g_h[nxt] + (size_t)(b * NW) * NS + s0;
#pragma unroll
    for (int oo = 0; oo < 8; oo++) {
        int o = og * 8 + oo;
        float2 v0 = up2(acc[oo][0]), v1 = up2(acc[oo][1]);
        float2 v2 = up2(acc[oo][2]), v3 = up2(acc[oo][3]);
        float4 w0 = make_float4(ftanh(v0.x), ftanh(v0.y), ftanh(v1.x), ftanh(v1.y));
        float4 w1 = make_float4(ftanh(v2.x), ftanh(v2.y), ftanh(v3.x), ftanh(v3.y));
        *(float4*)&dst[(size_t)o * NS + sg * 4] = w0;
        *(float4*)&dst[(size_t)o * NS + 128 + sg * 4] = w1;
    }
}

// ================= head =================
__global__ void __launch_bounds__(256) k_head(const float* __restrict__ qw,
                                              const float* __restrict__ qb,
                                              const float* __restrict__ ow,
                                              const float* __restrict__ ob,
                                              float* __restrict__ out, int cur) {
    __shared__ float Aq[64 * 36];
    __shared__ float Bq[32 * 260];
    int t = threadIdx.x;
    int qg = t >> 5, sg = t & 31;
    int b = blockIdx.y;
    int s0 = blockIdx.x * 256;
    for (int idx = t; idx < 64 * 32; idx += 256) {
        int i = idx >> 5, q = idx & 31;
        Aq[i * 36 + q] = qw[i * 32 + q];
    }
    unsigned long long acc[4][4];
#pragma unroll
    for (int qq = 0; qq < 4; qq++)
#pragma unroll
        for (int sp = 0; sp < 4; sp++) acc[qq][sp] = 0ull;

    const float* hb = g_h[cur] + (size_t)(b * NW) * NS;
    for (int ch = 0; ch < 4; ch++) {
        __syncthreads();
#pragma unroll
        for (int it = 0; it < 16; it++)
            Bq[it * 260 + t] = hb[(size_t)(ch * 16 + it) * NS + s0 + t];
        __syncthreads();
#pragma unroll 4
        for (int it = 0; it < 16; it++) {
            int i = ch * 16 + it;
            float4 a0 = *(const float4*)&Aq[i * 36 + qg * 4];
            ulonglong2 B0 = *(const ulonglong2*)&Bq[it * 260 + sg * 4];
            ulonglong2 B1 = *(const ulonglong2*)&Bq[it * 260 + 128 + sg * 4];
            unsigned long long ad;
            ad = pk2(a0.x);
            fma2(acc[0][0], ad, B0.x); fma2(acc[0][1], ad, B0.y);
            fma2(acc[0][2], ad, B1.x); fma2(acc[0][3], ad, B1.y);
            ad = pk2(a0.y);
            fma2(acc[1][0], ad, B0.x); fma2(acc[1][1], ad, B0.y);
            fma2(acc[1][2], ad, B1.x); fma2(acc[1][3], ad, B1.y);
            ad = pk2(a0.z);
            fma2(acc[2][0], ad, B0.x); fma2(acc[2][1], ad, B0.y);
            fma2(acc[2][2], ad, B1.x); fma2(acc[2][3], ad, B1.y);
            ad = pk2(a0.w);
            fma2(acc[3][0], ad, B0.x); fma2(acc[3][1], ad, B0.y);
            fma2(acc[3][2], ad, B1.x); fma2(acc[3][3], ad, B1.y);
        }
    }
    __syncthreads();
#pragma unroll
    for (int qq = 0; qq < 4; qq++) {
        int q = qg * 4 + qq;
        float qbv = qb[q];
#pragma unroll
        for (int sp = 0; sp < 4; sp++) {
            float2 v = up2(acc[qq][sp]);
            int sl = (sp >> 1) * 128 + sg * 4 + (sp & 1) * 2;
            Bq[q * 260 + sl] = ftanh(v.x + qbv);
            Bq[q * 260 + sl + 1] = ftanh(v.y + qbv);
        }
    }
    __syncthreads();
    float r = ob[0];
#pragma unroll 8
    for (int q = 0; q < 32; q++) r = fmaf(Bq[q * 260 + t], ow[q], r);
    out[(size_t)b * NS + s0 + t] = r;
}

// ================= launcher =================
extern "C" void kernel_launch(void* const* d_in, const int* in_sizes, int n_in,
                              void* d_out, int out_size) {
    const float* x  = (const float*)d_in[0];
    const float* pw = (const float*)d_in[1];
    const float* pb = (const float*)d_in[2];
    const float* wr = (const float*)d_in[3];
    const float* wi = (const float*)d_in[4];
    const float* cw = (const float*)d_in[5];
    const float* cb = (const float*)d_in[6];
    const float* qw = (const float*)d_in[7];
    const float* qb = (const float*)d_in[8];
    const float* ow = (const float*)d_in[9];
    const float* ob = (const float*)d_in[10];
    float* out = (float*)d_out;

    k_tab<<<NS / 256, 256>>>();
    k_prep<<<1, 64>>>(cw, pw, pb);
    k_xdft<<<NB, 256>>>(x);
    k_ft0<<<(NB * NW * NC) / 256, 256>>>(pw, pb);
    k_mix2<<<dim3(NM, 4), 256>>>(wr, wi, cb, 0);
    k_inv0<<<dim3(NS / 256, NB), 256>>>(x, 0);
    int cur = 0;
    for (int l = 1; l < NL; l++) {
        k_fwd<<<dim3(NSPLIT, NB), 64>>>(cur);
        k_red<<<(NB * NW * NC) / 256, 256>>>();
        k_mix2<<<dim3(NM, 4), 256>>>(wr, wi, cb, l);
        k_inv<<<dim3(NS / 256, NB), 256>>>(cw, l, cur, 1 - cur);
        cur ^= 1;
    }
    k_head<<<dim3(NS / 256, NB), 256>>>(qw, qb, ow, ob, out, cur);
}

// round 6
// speedup vs baseline: 1.5804x; 1.1417x over previous
#include <cuda_runtime.h>
#include <math.h>

#define NB 64
#define NS 8192
#define NW 64
#define NM 16
#define NC 32
#define NL 4
#define NSPLIT 16
#define SCH (NS / NSPLIT)

// ---------------- device scratch (no cudaMalloc allowed) ----------------
__device__ float g_h[2][NB * NW * NS];        // ping-pong activations (b,i,s)
__device__ float g_tab[NC * NS];              // [kc][s]: rows 0..15 cos, 16..31 sin
__device__ float g_tab2[NS * NC];             // [s][kc] transposed copy
__device__ float g_ftp[NSPLIT][NB * NW * NC]; // split-K partial DFT sums
__device__ float g_ft[NB * NW * NC];          // reduced: fr rows 0..15, fi rows 16..31
__device__ float g_coef[NB * NW * NC];        // per (b,o): A(cos) 0..15, B(sin) 16..31
__device__ float g_xft[NB * 2 * NC];          // DFT of x channels
__device__ float g_cw0[2 * NW];               // conv_w[0] @ p_w^T  : [c][o]
__device__ float g_b0[NW];                    // conv_w[0] @ p_b    : [o]

// ---------------- packed f32x2 + cp.async helpers ----------------
static __device__ __forceinline__ void fma2(unsigned long long& d,
                                            unsigned long long a,
                                            unsigned long long b) {
    asm("fma.rn.f32x2 %0, %1, %2, %0;" : "+l"(d) : "l"(a), "l"(b));
}
static __device__ __forceinline__ unsigned long long pk2(float v) {
    unsigned long long r;
    asm("mov.b64 %0, {%1, %1};" : "=l"(r) : "f"(v));
    return r;
}
static __device__ __forceinline__ float2 up2(unsigned long long p) {
    float2 r;
    asm("mov.b64 {%0, %1}, %2;" : "=f"(r.x), "=f"(r.y) : "l"(p));
    return r;
}
#define CPA16(dst_u32, src_ptr) \
    asm volatile("cp.async.cg.shared.global [%0], [%1], 16;" :: "r"(dst_u32), "l"(src_ptr))
#define CPC() asm volatile("cp.async.commit_group;")
#define CPW(N) asm volatile("cp.async.wait_group %0;" :: "n"(N))
static __device__ __forceinline__ unsigned s2u(const void* p) {
    return (unsigned)__cvta_generic_to_shared(p);
}

// fast accurate tanh: 2 MUFU (EX2 + RCP), ~1e-6 abs error
static __device__ __forceinline__ float ftanh(float x) {
    float ax = fminf(fabsf(x), 10.0f);
    float e = __expf(2.0f * ax);
    float t = (e - 1.0f) * __fdividef(1.0f, e + 1.0f);
    return copysignf(t, x);
}

// ================= basis tables + layer-0 folded weights =================
__global__ void k_tab(const float* __restrict__ cw, const float* __restrict__ pw,
                      const float* __restrict__ pb) {
    int t = threadIdx.x;
    if (blockIdx.x == 32) {            // prep block: g_cw0, g_b0
        int o = t;
        if (o >= NW) return;
        float c0 = 0.f, c1 = 0.f, bv = 0.f;
#pragma unroll 8
        for (int i = 0; i < NW; i++) {
            float w = cw[o * NW + i];
            c0 = fmaf(w, pw[i], c0);
            c1 = fmaf(w, pw[NW + i], c1);
            bv = fmaf(w, pb[i], bv);
        }
        g_cw0[o] = c0;
        g_cw0[NW + o] = c1;
        g_b0[o] = bv;
        return;
    }
    int s = blockIdx.x * 256 + t;
#pragma unroll
    for (int k = 0; k < NM; k++) {
        int ph = (k * s) & (NS - 1);
        float ang = (float)((double)ph * (6.283185307179586476925287 / (double)NS));
        float c, sn;
        sincosf(ang, &c, &sn);
        g_tab[k * NS + s] = c;
        g_tab[(k + NM) * NS + s] = sn;
        g_tab2[s * NC + k] = c;
        g_tab2[s * NC + NM + k] = sn;
    }
}

// ================= DFT of raw input x (2 channels) =================
__global__ void __launch_bounds__(256) k_xdft(const float* __restrict__ x) {
    int t = threadIdx.x;
    int w = t >> 5, lane = t & 31;
    int b = blockIdx.x;
    const float2* x2 = (const float2*)x + (size_t)b * NS;
    int k0 = w * 4;
    float acc[2][4];
#pragma unroll
    for (int c = 0; c < 2; c++)
#pragma unroll
        for (int k = 0; k < 4; k++) acc[c][k] = 0.f;
    for (int s = lane; s < NS; s += 32) {
        float2 xv = x2[s];
#pragma unroll
        for (int k = 0; k < 4; k++) {
            float tv = g_tab[(k0 + k) * NS + s];
            acc[0][k] = fmaf(xv.x, tv, acc[0][k]);
            acc[1][k] = fmaf(xv.y, tv, acc[1][k]);
        }
    }
#pragma unroll
    for (int off = 16; off > 0; off >>= 1)
#pragma unroll
        for (int c = 0; c < 2; c++)
#pragma unroll
            for (int k = 0; k < 4; k++)
                acc[c][k] += __shfl_xor_sync(0xffffffffu, acc[c][k], off);
    if (lane == 0) {
#pragma unroll
        for (int c = 0; c < 2; c++)
#pragma unroll
            for (int k = 0; k < 4; k++) {
                int kc = k0 + k;
                float v = acc[c][k] * (1.0f / NS);
                g_xft[(b * 2 + c) * NC + kc] = (kc < NM) ? v : -v;
            }
    }
}

// ================= forward DFT partials (layers >= 1) =================
// block (split, b), 128 threads; C[64 i][32 kc] over 512 samples.
// 32-sample chunks, cp.async double-buffered, f32x2 packed over kc.
__global__ void __launch_bounds__(128) k_fwd(int cur) {
    __shared__ float Hs[2][64 * 32];   // [i][s]  (phase-broadcast reads, no pad)
    __shared__ float Ts[2][32 * 32];   // [s][kc]
    int t = threadIdx.x;
    int kg = t & 7, ig = t >> 3;
    int i0 = ig * 4, kc0 = kg * 4;
    int b = blockIdx.y;
    int s0 = blockIdx.x * SCH;
    const float* hb = g_h[cur] + (size_t)(b * NW) * NS;

    unsigned long long acc[4][2];
#pragma unroll
    for (int j = 0; j < 4; j++) { acc[j][0] = 0ull; acc[j][1] = 0ull; }

#define FWD_STAGE(c, bf) do {                                                   \
        int soff = s0 + (c) * 32;                                               \
        _Pragma("unroll")                                                       \
        for (int k2 = 0; k2 < 4; k2++) {                                        \
            int q = t + k2 * 128;                                               \
            int i = q >> 3, pc = q & 7;                                         \
            CPA16(s2u(&Hs[bf][i * 32 + pc * 4]),                                \
                  hb + (size_t)i * NS + soff + pc * 4);                         \
        }                                                                       \
        _Pragma("unroll")                                                       \
        for (int k2 = 0; k2 < 2; k2++) {                                        \
            int q = t + k2 * 128;                                               \
            int sr = q >> 3, pc = q & 7;                                        \
            CPA16(s2u(&Ts[bf][sr * 32 + pc * 4]),                               \
                  g_tab2 + (size_t)(soff + sr) * NC + pc * 4);                  \
        }                                                                       \
        CPC();                                                                  \
    } while (0)

    FWD_STAGE(0, 0);
    const int NCH = SCH / 32;   // 16
    for (int c = 0; c < NCH; c++) {
        if (c + 1 < NCH) { FWD_STAGE(c + 1, (c + 1) & 1); CPW(1); }
        else CPW(0);
        __syncthreads();
        const float* Hc = Hs[c & 1];
        const float* Tc = Ts[c & 1];
#pragma unroll 4
        for (int s = 0; s < 32; s += 4) {
            float4 hv[4];
#pragma unroll
            for (int j = 0; j < 4; j++)
                hv[j] = *(const float4*)&Hc[(i0 + j) * 32 + s];
#pragma unroll
            for (int ss = 0; ss < 4; ss++) {
                ulonglong2 tb = *(const ulonglong2*)&Tc[(s + ss) * 32 + kc0];
#pragma unroll
                for (int j = 0; j < 4; j++) {
                    float h = (ss == 0) ? hv[j].x : (ss == 1) ? hv[j].y
                             : (ss == 2) ? hv[j].z : hv[j].w;
                    unsigned long long a = pk2(h);
                    fma2(acc[j][0], a, tb.x);
                    fma2(acc[j][1], a, tb.y);
                }
            }
        }
        __syncthreads();
    }
    float* fp = g_ftp[blockIdx.x] + (b * NW) * NC;
#pragma unroll
    for (int j = 0; j < 4; j++) {
        float2 c0 = up2(acc[j][0]), c1 = up2(acc[j][1]);
        *(float4*)&fp[(i0 + j) * NC + kc0] = make_float4(c0.x, c0.y, c1.x, c1.y);
    }
#undef FWD_STAGE
}

// ================= split-K reduce =================
__global__ void __launch_bounds__(256) k_red() {
    int idx = blockIdx.x * 256 + threadIdx.x;
    float v = 0.f;
#pragma unroll
    for (int sp = 0; sp < NSPLIT; sp++) v += g_ftp[sp][idx];
    int kc = idx & 31;
    g_ft[idx] = (kc < NM ? v : -v) * (1.0f / NS);
}

// ================= mode mix (l==0 reads x-spectrum directly) =================
__global__ void __launch_bounds__(256) k_mix2(const float* __restrict__ wr,
                                              const float* __restrict__ wi,
                                              const float* __restrict__ cb, int l,
                                              const float* __restrict__ pw,
                                              const float* __restrict__ pb) {
    __shared__ float wrs[64 * 65], wis[64 * 65];
    __shared__ float frs[16 * 64], fis[16 * 64];
    int t = threadIdx.x;
    int k = blockIdx.x, bg = blockIdx.y;
    const float* wrl = wr + (size_t)l * NW * NW * NM;
    const float* wil = wi + (size_t)l * NW * NW * NM;
    for (int idx = t; idx < 4096; idx += 256) {
        int i = idx >> 6, o = idx & 63;
        wrs[i * 65 + o] = wrl[(i * 64 + o) * NM + k];
        wis[i * 65 + o] = wil[(i * 64 + o) * NM + k];
    }
    for (int idx = t; idx < 1024; idx += 256) {
        int b16 = idx >> 6, i = idx & 63;
        int b = bg * 16 + b16;
        if (l == 0) {
            float x0c = g_xft[(b * 2) * NC + k],      x1c = g_xft[(b * 2 + 1) * NC + k];
            float x0s = g_xft[(b * 2) * NC + NM + k], x1s = g_xft[(b * 2 + 1) * NC + NM + k];
            float fr = pw[i] * x0c + pw[NW + i] * x1c;
            if (k == 0) fr += pb[i];
            frs[b16 * 64 + i] = fr;
            fis[b16 * 64 + i] = pw[i] * x0s + pw[NW + i] * x1s;
        } else {
            frs[b16 * 64 + i] = g_ft[(b * NW + i) * NC + k];
            fis[b16 * 64 + i] = g_ft[(b * NW + i) * NC + NM + k];
        }
    }
    __syncthreads();
#pragma unroll
    for (int u = 0; u < 4; u++) {
        int oi = t + u * 256;
        int o = oi & 63, b16 = oi >> 6;
        float sr = 0.f, si = 0.f;
#pragma unroll 8
        for (int i = 0; i < 64; i++) {
            float fr = frs[b16 * 64 + i], fi = fis[b16 * 64 + i];
            float a = wrs[i * 65 + o], c = wis[i * 65 + o];
            sr = fmaf(fr, a, sr); sr = fmaf(-fi, c, sr);
            si = fmaf(fr, c, si); si = fmaf(fi, a, si);
        }
        int b = bg * 16 + b16;
        float* cf = g_coef + (b * NW + o) * NC;
        if (k == 0) {
            float base = sr + cb[l * NW + o];
            if (l == 0) base += g_b0[o];
            cf[0] = base; cf[NM] = 0.f;
        } else { cf[k] = 2.f * sr; cf[NM + k] = -2.f * si; }
    }
}

// 32 fma2 on one (B0,B1) pair against 8 broadcast A values
#define GEMM_STEP(Asrc, B0, B1) do {                                            \
        float4 a0 = *(const float4*)&(Asrc)[0];                                 \
        float4 a1 = *(const float4*)&(Asrc)[4];                                 \
        unsigned long long ad;                                                  \
        ad = pk2(a0.x);                                                         \
        fma2(acc[0][0], ad, B0.x); fma2(acc[0][1], ad, B0.y);                   \
        fma2(acc[0][2], ad, B1.x); fma2(acc[0][3], ad, B1.y);                   \
        ad = pk2(a0.y);                                                         \
        fma2(acc[1][0], ad, B0.x); fma2(acc[1][1], ad, B0.y);                   \
        fma2(acc[1][2], ad, B1.x); fma2(acc[1][3], ad, B1.y);                   \
        ad = pk2(a0.z);                                                         \
        fma2(acc[2][0], ad, B0.x); fma2(acc[2][1], ad, B0.y);                   \
        fma2(acc[2][2], ad, B1.x); fma2(acc[2][3], ad, B1.y);                   \
        ad = pk2(a0.w);                                                         \
        fma2(acc[3][0], ad, B0.x); fma2(acc[3][1], ad, B0.y);                   \
        fma2(acc[3][2], ad, B1.x); fma2(acc[3][3], ad, B1.y);                   \
        ad = pk2(a1.x);                                                         \
        fma2(acc[4][0], ad, B0.x); fma2(acc[4][1], ad, B0.y);                   \
        fma2(acc[4][2], ad, B1.x); fma2(acc[4][3], ad, B1.y);                   \
        ad = pk2(a1.y);                                                         \
        fma2(acc[5][0], ad, B0.x); fma2(acc[5][1], ad, B0.y);                   \
        fma2(acc[5][2], ad, B1.x); fma2(acc[5][3], ad, B1.y);                   \
        ad = pk2(a1.z);                                                         \
        fma2(acc[6][0], ad, B0.x); fma2(acc[6][1], ad, B0.y);                   \
        fma2(acc[6][2], ad, B1.x); fma2(acc[6][3], ad, B1.y);                   \
        ad = pk2(a1.w);                                                         \
        fma2(acc[7][0], ad, B0.x); fma2(acc[7][1], ad, B0.y);                   \
        fma2(acc[7][2], ad, B1.x); fma2(acc[7][3], ad, B1.y);                   \
    } while (0)

// ================= fused irfft + conv + tanh (layers >= 1) =================
// A-tile stride 64 (broadcast reads); B double-buffered in 8-row chunks.
__global__ void __launch_bounds__(256) k_inv(const float* __restrict__ cw, int l,
                                             int cur, int nxt) {
    __shared__ float Ad[96 * 64];
    __shared__ float Bs[2][8 * 260];
    int t = threadIdx.x;
    int og = t >> 5, sg = t & 31;
    int b = blockIdx.y;
    int s0 = blockIdx.x * 256;
    const float* cf = g_coef + (b * NW) * NC;
    for (int idx = t; idx < 96 * 64; idx += 256) {
        int r = idx >> 6, o = idx & 63;
        Ad[r * 64 + o] = (r < 32) ? cf[o * NC + r]
                                  : cw[(l * NW + o) * NW + (r - 32)];
    }
    const float* hb = g_h[cur] + (size_t)(b * NW) * NS;

#define INV_STAGE(ch, bf) do {                                                  \
        _Pragma("unroll")                                                       \
        for (int k2 = 0; k2 < 2; k2++) {                                        \
            int q = t + k2 * 256;                                               \
            int it = q >> 6, pc = q & 63;                                       \
            int j = (ch) * 8 + it;                                              \
            const float* src = (j < 32)                                         \
                ? (g_tab + (size_t)j * NS + s0 + pc * 4)                        \
                : (hb + (size_t)(j - 32) * NS + s0 + pc * 4);                   \
            CPA16(s2u(&Bs[bf][it * 260 + pc * 4]), src);                        \
        }                                                                       \
        CPC();                                                                  \
    } while (0)

    unsigned long long acc[8][4];
#pragma unroll
    for (int oo = 0; oo < 8; oo++)
#pragma unroll
        for (int sp = 0; sp < 4; sp++) acc[oo][sp] = 0ull;

    INV_STAGE(0, 0);
    for (int ch = 0; ch < 12; ch++) {
        if (ch < 11) { INV_STAGE(ch + 1, (ch + 1) & 1); CPW(1); }
        else CPW(0);
        __syncthreads();
        const float* Bc = Bs[ch & 1];
#pragma unroll
        for (int it = 0; it < 8; it++) {
            int j = ch * 8 + it;
            ulonglong2 B0 = *(const ulonglong2*)&Bc[it * 260 + sg * 4];
            ulonglong2 B1 = *(const ulonglong2*)&Bc[it * 260 + 128 + sg * 4];
            GEMM_STEP(&Ad[j * 64 + og * 8], B0, B1);
        }
        __syncthreads();
    }
#undef INV_STAGE
    float* dst = g_h[nxt] + (size_t)(b * NW) * NS + s0;
#pragma unroll
    for (int oo = 0; oo < 8; oo++) {
        int o = og * 8 + oo;
        float2 v0 = up2(acc[oo][0]), v1 = up2(acc[oo][1]);
        float2 v2 = up2(acc[oo][2]), v3 = up2(acc[oo][3]);
        float4 w0 = make_float4(ftanh(v0.x), ftanh(v0.y), ftanh(v1.x), ftanh(v1.y));
        float4 w1 = make_float4(ftanh(v2.x), ftanh(v2.y), ftanh(v3.x), ftanh(v3.y));
        *(float4*)&dst[(size_t)o * NS + sg * 4] = w0;
        *(float4*)&dst[(size_t)o * NS + 128 + sg * 4] = w1;
    }
}

// ================= layer-0 fused inverse: K = 32 basis + 2 x channels =================
__global__ void __launch_bounds__(256) k_inv0(const float* __restrict__ x, int nxt) {
    __shared__ float Ad[34 * 68];
    __shared__ float Bs[2][16 * 260];
    int t = threadIdx.x;
    int og = t >> 5, sg = t & 31;
    int b = blockIdx.y;
    int s0 = blockIdx.x * 256;
    const float* cf = g_coef + (b * NW) * NC;
    for (int idx = t; idx < 34 * 64; idx += 256) {
        int r = idx >> 6, o = idx & 63;
        Ad[r * 68 + o] = (r < 32) ? cf[o * NC + r] : g_cw0[(r - 32) * NW + o];
    }
    unsigned long long acc[8][4];
#pragma unroll
    for (int oo = 0; oo < 8; oo++)
#pragma unroll
        for (int sp = 0; sp < 4; sp++) acc[oo][sp] = 0ull;

    // prefetch both tab chunks
#pragma unroll
    for (int ch = 0; ch < 2; ch++) {
#pragma unroll
        for (int k2 = 0; k2 < 4; k2++) {
            int q = t + k2 * 256;
            int it = q >> 6, pc = q & 63;
            int j = ch * 16 + it;
            CPA16(s2u(&Bs[ch][it * 260 + pc * 4]),
                  g_tab + (size_t)j * NS + s0 + pc * 4);
        }
        CPC();
    }
    for (int ch = 0; ch < 2; ch++) {
        if (ch == 0) CPW(1); else CPW(0);
        __syncthreads();
        const float* Bc = Bs[ch];
#pragma unroll 4
        for (int it = 0; it < 16; it++) {
            int j = ch * 16 + it;
            ulonglong2 B0 = *(const ulonglong2*)&Bc[it * 260 + sg * 4];
            ulonglong2 B1 = *(const ulonglong2*)&Bc[it * 260 + 128 + sg * 4];
            GEMM_STEP(&Ad[j * 68 + og * 8], B0, B1);
        }
        __syncthreads();
    }
    // x-channel rows (interleaved source -> manual stage)
    {
        const float2* x2 = (const float2*)x + (size_t)b * NS + s0;
        float2 xv = x2[t];
        Bs[0][0 * 260 + t] = xv.x;
        Bs[0][1 * 260 + t] = xv.y;
    }
    __syncthreads();
#pragma unroll
    for (int it = 0; it < 2; it++) {
        int j = 32 + it;
        ulonglong2 B0 = *(const ulonglong2*)&Bs[0][it * 260 + sg * 4];
        ulonglong2 B1 = *(const ulonglong2*)&Bs[0][it * 260 + 128 + sg * 4];
        GEMM_STEP(&Ad[j * 68 + og * 8], B0, B1);
    }
    float* dst = g_h[nxt] + (size_t)(b * NW) * NS + s0;
#pragma unroll
    for (int oo = 0; oo < 8; oo++) {
        int o = og * 8 + oo;
        float2 v0 = up2(acc[oo][0]), v1 = up2(acc[oo][1]);
        float2 v2 = up2(acc[oo][2]), v3 = up2(acc[oo][3]);
        float4 w0 = make_float4(ftanh(v0.x), ftanh(v0.y), ftanh(v1.x), ftanh(v1.y));
        float4 w1 = make_float4(ftanh(v2.x), ftanh(v2.y), ftanh(v3.x), ftanh(v3.y));
        *(float4*)&dst[(size_t)o * NS + sg * 4] = w0;
        *(float4*)&dst[(size_t)o * NS + 128 + sg * 4] = w1;
    }
}

// ================= head =================
__global__ void __launch_bounds__(256) k_head(const float* __restrict__ qw,
                                              const float* __restrict__ qb,
                                              const float* __restrict__ ow,
                                              const float* __restrict__ ob,
                                              float* __restrict__ out, int cur) {
    __shared__ float Aq[64 * 36];
    __shared__ float Bq[2][16 * 260];   // halves alternate as chunk buffers, then qa
    int t = threadIdx.x;
    int qg = t >> 5, sg = t & 31;
    int b = blockIdx.y;
    int s0 = blockIdx.x * 256;
    for (int idx = t; idx < 64 * 32; idx += 256) {
        int i = idx >> 5, q = idx & 31;
        Aq[i * 36 + q] = qw[i * 32 + q];
    }
    unsigned long long acc[4][4];
#pragma unroll
    for (int qq = 0; qq < 4; qq++)
#pragma unroll
        for (int sp = 0; sp < 4; sp++) acc[qq][sp] = 0ull;

    const float* hb = g_h[cur] + (size_t)(b * NW) * NS;
#define HEAD_STAGE(ch, bf) do {                                                 \
        _Pragma("unroll")                                                       \
        for (int k2 = 0; k2 < 4; k2++) {                                        \
            int q = t + k2 * 256;                                               \
            int it = q >> 6, pc = q & 63;                                       \
            CPA16(s2u(&Bq[bf][it * 260 + pc * 4]),                              \
                  hb + (size_t)((ch) * 16 + it) * NS + s0 + pc * 4);            \
        }                                                                       \
        CPC();                                                                  \
    } while (0)

    HEAD_STAGE(0, 0);
    for (int ch = 0; ch < 4; ch++) {
        if (ch < 3) { HEAD_STAGE(ch + 1, (ch + 1) & 1); CPW(1); }
        else CPW(0);
        __syncthreads();
        const float* Bc = Bq[ch & 1];
#pragma unroll 4
        for (int it = 0; it < 16; it++) {
            int i = ch * 16 + it;
            float4 a0 = *(const float4*)&Aq[i * 36 + qg * 4];
            ulonglong2 B0 = *(const ulonglong2*)&Bc[it * 260 + sg * 4];
            ulonglong2 B1 = *(const ulonglong2*)&Bc[it * 260 + 128 + sg * 4];
            unsigned long long ad;
            ad = pk2(a0.x);
            fma2(acc[0][0], ad, B0.x); fma2(acc[0][1], ad, B0.y);
            fma2(acc[0][2], ad, B1.x); fma2(acc[0][3], ad, B1.y);
            ad = pk2(a0.y);
            fma2(acc[1][0], ad, B0.x); fma2(acc[1][1], ad, B0.y);
            fma2(acc[1][2], ad, B1.x); fma2(acc[1][3], ad, B1.y);
            ad = pk2(a0.z);
            fma2(acc[2][0], ad, B0.x); fma2(acc[2][1], ad, B0.y);
            fma2(acc[2][2], ad, B1.x); fma2(acc[2][3], ad, B1.y);
            ad = pk2(a0.w);
            fma2(acc[3][0], ad, B0.x); fma2(acc[3][1], ad, B0.y);
            fma2(acc[3][2], ad, B1.x); fma2(acc[3][3], ad, B1.y);
        }
        __syncthreads();
    }
#undef HEAD_STAGE
    float* BQ = &Bq[0][0];   // reuse both halves as qa[32][260]
#pragma unroll
    for (int qq = 0; qq < 4; qq++) {
        int q = qg * 4 + qq;
        float qbv = qb[q];
#pragma unroll
        for (int sp = 0; sp < 4; sp++) {
            float2 v = up2(acc[qq][sp]);
            int sl = (sp >> 1) * 128 + sg * 4 + (sp & 1) * 2;
            BQ[q * 260 + sl] = ftanh(v.x + qbv);
            BQ[q * 260 + sl + 1] = ftanh(v.y + qbv);
        }
    }
    __syncthreads();
    float r = ob[0];
#pragma unroll 8
    for (int q = 0; q < 32; q++) r = fmaf(BQ[q * 260 + t], ow[q], r);
    out[(size_t)b * NS + s0 + t] = r;
}

// ================= launcher =================
extern "C" void kernel_launch(void* const* d_in, const int* in_sizes, int n_in,
                              void* d_out, int out_size) {
    const float* x  = (const float*)d_in[0];
    const float* pw = (const float*)d_in[1];
    const float* pb = (const float*)d_in[2];
    const float* wr = (const float*)d_in[3];
    const float* wi = (const float*)d_in[4];
    const float* cw = (const float*)d_in[5];
    const float* cb = (const float*)d_in[6];
    const float* qw = (const float*)d_in[7];
    const float* qb = (const float*)d_in[8];
    const float* ow = (const float*)d_in[9];
    const float* ob = (const float*)d_in[10];
    float* out = (float*)d_out;

    k_tab<<<33, 256>>>(cw, pw, pb);                       // 1
    k_xdft<<<NB, 256>>>(x);                               // 2
    k_mix2<<<dim3(NM, 4), 256>>>(wr, wi, cb, 0, pw, pb);  // 3
    k_inv0<<<dim3(NS / 256, NB), 256>>>(x, 0);            // 4  <- profiled slot
    int cur = 0;
    for (int l = 1; l < NL; l++) {
        k_fwd<<<dim3(NSPLIT, NB), 128>>>(cur);
        k_red<<<(NB * NW * NC) / 256, 256>>>();
        k_mix2<<<dim3(NM, 4), 256>>>(wr, wi, cb, l, pw, pb);
        k_inv<<<dim3(NS / 256, NB), 256>>>(cw, l, cur, 1 - cur);
        cur ^= 1;
    }
    k_head<<<dim3(NS / 256, NB), 256>>>(qw, qb, ow, ob, out, cur);
}